// round 3
// baseline (speedup 1.0000x reference)
#include <cuda_runtime.h>
#include <math.h>

#define NQ 10
#define NP 100
#define FD 256
#define NOUT 30
#define TWO_PI_F 6.2831853071795864769f

// Named barrier per branch-group (ids 1..3), 128 threads each.
__device__ __forceinline__ void gbar(int g) {
    asm volatile("bar.sync %0, 128;" :: "r"(g + 1) : "memory");
}

// Fused SU(2) 1q gate on amplitude-bit b. U = [[u00,u01],[-conj(u01),conj(u00)]]
// State: 8 amps/thread, amp = (gtid<<3)|j. j bits 0-2 local, gtid bits 0-4 lane
// (amp bits 3-7), gtid bits 5-6 warp (amp bits 8-9).
__device__ __forceinline__ void apply_u(int b, float u00r, float u00i,
                                        float u01r, float u01i,
                                        float ar[8], float ai[8],
                                        int gtid, float* B, int g) {
    if (b < 3) {                                  // local register pairs
#pragma unroll
        for (int t = 0; t < 4; t++) {
            const int lm = (1 << b) - 1;
            const int j0 = ((t & ~lm) << 1) | (t & lm);
            const int j1 = j0 | (1 << b);
            float r0 = ar[j0], i0 = ai[j0], r1 = ar[j1], i1 = ai[j1];
            ar[j0] =  u00r * r0 - u00i * i0 + u01r * r1 - u01i * i1;
            ai[j0] =  u00r * i0 + u00i * r0 + u01r * i1 + u01i * r1;
            ar[j1] = -u01r * r0 - u01i * i0 + u00r * r1 + u00i * i1;
            ai[j1] = -u01r * i0 + u01i * r0 + u00r * i1 - u00i * r1;
        }
    } else if (b < 8) {                           // lane bits: warp shuffle
        const int m = 1 << (b - 3);
        const int s = (gtid >> (b - 3)) & 1;
        const float cwr = u00r, cwi = s ? -u00i : u00i;
        const float cpr = s ? -u01r : u01r, cpi = u01i;
#pragma unroll
        for (int j = 0; j < 8; j++) {
            float pr = __shfl_xor_sync(0xffffffffu, ar[j], m);
            float pi = __shfl_xor_sync(0xffffffffu, ai[j], m);
            float orr = ar[j], oii = ai[j];
            ar[j] = cwr * orr - cwi * oii + cpr * pr - cpi * pi;
            ai[j] = cwr * oii + cwi * orr + cpr * pi + cpi * pr;
        }
    } else {                                      // warp bits: smem exchange
        const int m = 1 << (b - 3);
        const int s = (gtid >> (b - 3)) & 1;
        float4* A4 = (float4*)B;
        float4* I4 = (float4*)(B + 1024);
        A4[gtid * 2]     = make_float4(ar[0], ar[1], ar[2], ar[3]);
        A4[gtid * 2 + 1] = make_float4(ar[4], ar[5], ar[6], ar[7]);
        I4[gtid * 2]     = make_float4(ai[0], ai[1], ai[2], ai[3]);
        I4[gtid * 2 + 1] = make_float4(ai[4], ai[5], ai[6], ai[7]);
        gbar(g);
        const int pt = gtid ^ m;
        float4 pa0 = A4[pt * 2], pa1 = A4[pt * 2 + 1];
        float4 pb0 = I4[pt * 2], pb1 = I4[pt * 2 + 1];
        float prr[8] = {pa0.x, pa0.y, pa0.z, pa0.w, pa1.x, pa1.y, pa1.z, pa1.w};
        float pii[8] = {pb0.x, pb0.y, pb0.z, pb0.w, pb1.x, pb1.y, pb1.z, pb1.w};
        const float cwr = u00r, cwi = s ? -u00i : u00i;
        const float cpr = s ? -u01r : u01r, cpi = u01i;
#pragma unroll
        for (int j = 0; j < 8; j++) {
            float orr = ar[j], oii = ai[j];
            ar[j] = cwr * orr - cwi * oii + cpr * prr[j] - cpi * pii[j];
            ai[j] = cwr * oii + cwi * orr + cpr * pii[j] + cpi * prr[j];
        }
        gbar(g);
    }
}

// Controlled-RX: control bit pc, target bit pt.
__device__ __forceinline__ void apply_crx(int pc, int pt, float c, float s,
                                          float ar[8], float ai[8],
                                          int gtid, float* B, int g) {
    const bool tc = (pc >= 3) ? (((gtid >> (pc - 3)) & 1) != 0) : true;
    if (pt < 3) {                                 // local target
#pragma unroll
        for (int t = 0; t < 4; t++) {
            const int lm = (1 << pt) - 1;
            const int j0 = ((t & ~lm) << 1) | (t & lm);
            const int j1 = j0 | (1 << pt);
            bool upd = tc && (pc < 3 ? (((j0 >> pc) & 1) != 0) : true);
            if (upd) {
                float r0 = ar[j0], i0 = ai[j0], r1 = ar[j1], i1 = ai[j1];
                ar[j0] = c * r0 + s * i1;  ai[j0] = c * i0 - s * r1;
                ar[j1] = c * r1 + s * i0;  ai[j1] = c * i1 - s * r0;
            }
        }
    } else if (pt < 8) {                          // lane target: shuffle
        const int m = 1 << (pt - 3);
#pragma unroll
        for (int j = 0; j < 8; j++) {
            float pr = __shfl_xor_sync(0xffffffffu, ar[j], m);
            float pi = __shfl_xor_sync(0xffffffffu, ai[j], m);
            bool upd = tc && (pc < 3 ? (((j >> pc) & 1) != 0) : true);
            if (upd) {
                float orr = ar[j], oii = ai[j];
                ar[j] = c * orr + s * pi;
                ai[j] = c * oii - s * pr;
            }
        }
    } else {                                      // warp target: smem exchange
        const int m = 1 << (pt - 3);
        float4* A4 = (float4*)B;
        float4* I4 = (float4*)(B + 1024);
        A4[gtid * 2]     = make_float4(ar[0], ar[1], ar[2], ar[3]);
        A4[gtid * 2 + 1] = make_float4(ar[4], ar[5], ar[6], ar[7]);
        I4[gtid * 2]     = make_float4(ai[0], ai[1], ai[2], ai[3]);
        I4[gtid * 2 + 1] = make_float4(ai[4], ai[5], ai[6], ai[7]);
        gbar(g);
        const int pidx = gtid ^ m;
        float4 pa0 = A4[pidx * 2], pa1 = A4[pidx * 2 + 1];
        float4 pb0 = I4[pidx * 2], pb1 = I4[pidx * 2 + 1];
        float prr[8] = {pa0.x, pa0.y, pa0.z, pa0.w, pa1.x, pa1.y, pa1.z, pa1.w};
        float pii[8] = {pb0.x, pb0.y, pb0.z, pb0.w, pb1.x, pb1.y, pb1.z, pb1.w};
#pragma unroll
        for (int j = 0; j < 8; j++) {
            bool upd = tc && (pc < 3 ? (((j >> pc) & 1) != 0) : true);
            if (upd) {
                float orr = ar[j], oii = ai[j];
                ar[j] = c * orr + s * pii[j];
                ai[j] = c * oii - s * prr[j];
            }
        }
        gbar(g);
    }
}

__global__ __launch_bounds__(384, 2)
void qsb_kernel(const float* __restrict__ x,
                const float* __restrict__ W1, const float* __restrict__ b1,
                const float* __restrict__ W2, const float* __restrict__ b2,
                const float* __restrict__ W3, const float* __restrict__ b3,
                const float* __restrict__ base1, const float* __restrict__ base2,
                const float* __restrict__ base3,
                const float* __restrict__ alpha_r, const float* __restrict__ alpha_i,
                const float* __restrict__ beta_r,  const float* __restrict__ beta_i,
                const float* __restrict__ gamma_r, const float* __restrict__ gamma_i,
                float* __restrict__ out) {
    __shared__ float sx[FD];
    __shared__ float gc[3][NP], gs[3][NP];
    __shared__ float buf[3][2048];                // per-group exchange / dump
    __shared__ float wred[3][4][NOUT];
    __shared__ float mres[3][NOUT];

    const int tid   = threadIdx.x;
    const int g     = tid >> 7;                   // branch group 0..2
    const int gtid  = tid & 127;
    const int lane  = tid & 31;
    const int gwarp = gtid >> 5;                  // 0..3
    const int batch = blockIdx.x;

    if (tid < FD) sx[tid] = x[batch * FD + tid];
    __syncthreads();

    const float* W  = (g == 0) ? W1 : ((g == 1) ? W2 : W3);
    const float* bb = (g == 0) ? b1 : ((g == 1) ? b2 : b3);
    const float* ba = (g == 0) ? base1 : ((g == 1) ? base2 : base3);

    // ---- params: linear + sigmoid -> (cos, sin)(theta/2), software-pipelined ----
    {
        const float4* xv = (const float4*)sx;
        const float4 x0 = xv[lane * 2];
        const float4 x1 = xv[lane * 2 + 1];
        int p = gwarp;
        const float4* Wv = (const float4*)(W + p * FD);
        float4 w0 = Wv[lane * 2], w1 = Wv[lane * 2 + 1];
        while (p < NP) {
            const int pn = p + 4;
            float4 nw0, nw1;
            if (pn < NP) {
                const float4* Wn = (const float4*)(W + pn * FD);
                nw0 = Wn[lane * 2]; nw1 = Wn[lane * 2 + 1];
            }
            float acc = w0.x * x0.x + w0.y * x0.y + w0.z * x0.z + w0.w * x0.w
                      + w1.x * x1.x + w1.y * x1.y + w1.z * x1.z + w1.w * x1.w;
#pragma unroll
            for (int o = 16; o; o >>= 1)
                acc += __shfl_down_sync(0xffffffffu, acc, o);
            if (lane == 0) {
                float t     = acc + bb[p] + ba[p];
                float sig   = 1.f / (1.f + __expf(-t));
                float theta = sig * TWO_PI_F;
                float sv, cv;
                __sincosf(0.5f * theta, &sv, &cv);
                gc[g][p] = cv; gs[g][p] = sv;
            }
            w0 = nw0; w1 = nw1; p = pn;
        }
    }
    gbar(g);

    // ---- state in registers: amp index = (gtid << 3) | j ----
    float ar[8], ai[8];
#pragma unroll
    for (int j = 0; j < 8; j++) { ar[j] = 0.f; ai[j] = 0.f; }
    if (gtid == 0) ar[0] = 1.f;

    float* B = buf[g];

    int idx = 0;
#pragma unroll
    for (int layer = 0; layer < 2; layer++) {
#pragma unroll
        for (int w = 0; w < NQ; w++) {
            const int b = 9 - w;
            float c0 = gc[g][idx],     s0 = gs[g][idx];
            float c1 = gc[g][idx + 1], s1 = gs[g][idx + 1];
            float cz = gc[g][idx + 2], sz = gs[g][idx + 2];
            idx += 3;
            // U = Rz * Ry * Rx (SU(2): u00, u01)
            float u00r =  cz * c1 * c0 + sz * s1 * s0;
            float u00i =  cz * s1 * s0 - sz * c1 * c0;
            float u01r = -(cz * s1 * c0 + sz * c1 * s0);
            float u01i =  sz * s1 * c0 - cz * c1 * s0;
            apply_u(b, u00r, u00i, u01r, u01i, ar, ai, gtid, B, g);
        }
#pragma unroll
        for (int i = 0; i < NQ; i++) {
            apply_crx(9 - i, 9 - ((i + 1) % NQ), gc[g][idx], gs[g][idx],
                      ar, ai, gtid, B, g);
            idx++;
        }
#pragma unroll
        for (int i = NQ - 1; i >= 0; i--) {
            apply_crx(9 - i, 9 - ((i + 9) % NQ), gc[g][idx], gs[g][idx],
                      ar, ai, gtid, B, g);
            idx++;
        }
    }

    // ---- dump state, compute expectations ----
    {
        float4* A4 = (float4*)B;
        float4* I4 = (float4*)(B + 1024);
        A4[gtid * 2]     = make_float4(ar[0], ar[1], ar[2], ar[3]);
        A4[gtid * 2 + 1] = make_float4(ar[4], ar[5], ar[6], ar[7]);
        I4[gtid * 2]     = make_float4(ai[0], ai[1], ai[2], ai[3]);
        I4[gtid * 2 + 1] = make_float4(ai[4], ai[5], ai[6], ai[7]);
        gbar(g);
    }
#pragma unroll
    for (int w = 0; w < NQ; w++) {
        const int p = 9 - w;
        float zr = 0.f, zi = 0.f, pz = 0.f;
#pragma unroll
        for (int kk = 0; kk < 4; kk++) {
            int k  = gtid + kk * 128;
            int i0 = ((k >> p) << (p + 1)) | (k & ((1 << p) - 1));
            int i1 = i0 | (1 << p);
            float r0 = B[i0], m0 = B[1024 + i0];
            float r1 = B[i1], m1 = B[1024 + i1];
            zr += r0 * r1 + m0 * m1;
            zi += r0 * m1 - m0 * r1;
            pz += (r0 * r0 + m0 * m0) - (r1 * r1 + m1 * m1);
        }
#pragma unroll
        for (int o = 16; o; o >>= 1) {
            zr += __shfl_down_sync(0xffffffffu, zr, o);
            zi += __shfl_down_sync(0xffffffffu, zi, o);
            pz += __shfl_down_sync(0xffffffffu, pz, o);
        }
        if (lane == 0) {
            wred[g][gwarp][w]          = zr;
            wred[g][gwarp][NQ + w]     = zi;
            wred[g][gwarp][2 * NQ + w] = pz;
        }
    }
    gbar(g);
    if (gtid < NOUT) {
        float a = wred[g][0][gtid] + wred[g][1][gtid]
                + wred[g][2][gtid] + wred[g][3][gtid];
        mres[g][gtid] = (gtid < 2 * NQ) ? 2.f * a : a;
    }
    __syncthreads();

    // ---- superposition combine ----
    if (tid < NOUT) {
        float arv = alpha_r[0], aiv = alpha_i[0];
        float brv = beta_r[0],  biv = beta_i[0];
        float grv = gamma_r[0], giv = gamma_i[0];
        float nrm = sqrtf(arv * arv + aiv * aiv + brv * brv + biv * biv +
                          grv * grv + giv * giv + 1e-9f);
        float inv = 1.f / nrm;
        float re = (arv * mres[0][tid] + brv * mres[1][tid] + grv * mres[2][tid]) * inv;
        float im = (aiv * mres[0][tid] + biv * mres[1][tid] + giv * mres[2][tid]) * inv;
        out[batch * NOUT + tid] = sqrtf(re * re + im * im);
    }
}

extern "C" void kernel_launch(void* const* d_in, const int* in_sizes, int n_in,
                              void* d_out, int out_size) {
    const float* x      = (const float*)d_in[0];
    const float* W1     = (const float*)d_in[1];
    const float* b1     = (const float*)d_in[2];
    const float* W2     = (const float*)d_in[3];
    const float* b2     = (const float*)d_in[4];
    const float* W3     = (const float*)d_in[5];
    const float* b3     = (const float*)d_in[6];
    const float* base1  = (const float*)d_in[7];
    const float* base2  = (const float*)d_in[8];
    const float* base3  = (const float*)d_in[9];
    const float* ar     = (const float*)d_in[10];
    const float* ai     = (const float*)d_in[11];
    const float* br     = (const float*)d_in[12];
    const float* bi     = (const float*)d_in[13];
    const float* gr     = (const float*)d_in[14];
    const float* gi     = (const float*)d_in[15];
    float* out = (float*)d_out;

    qsb_kernel<<<256, 384>>>(x, W1, b1, W2, b2, W3, b3, base1, base2, base3,
                             ar, ai, br, bi, gr, gi, out);
}

// round 4
// speedup vs baseline: 1.4250x; 1.4250x over previous
#include <cuda_runtime.h>
#include <math.h>

#define NQ 10
#define NP 100
#define FD 256
#define NOUT 30
#define TWO_PI_F 6.2831853071795864769f

// Inter-kernel scratch: per (branch, sample) expectation values (padded row 32).
__device__ float g_mres[3][256][32];

// ---------------------------------------------------------------------------
// Circuit kernel: one CTA = one (sample, branch). 256 threads, 4 amps/thread.
// amp = (tid << 2) | j : j bits 0-1 local, tid bits 0-4 lane (amp bits 2-6),
// tid bits 5-7 cross-warp (amp bits 7-9, via smem).
// ---------------------------------------------------------------------------

__device__ __forceinline__ void apply_u(int b, float u00r, float u00i,
                                        float u01r, float u01i,
                                        float ar[4], float ai[4],
                                        int tid, float* B) {
    if (b < 2) {                                  // local register pairs
#pragma unroll
        for (int t = 0; t < 2; t++) {
            int j0 = (b == 0) ? t * 2 : t;
            int j1 = j0 | (1 << b);
            float r0 = ar[j0], i0 = ai[j0], r1 = ar[j1], i1 = ai[j1];
            ar[j0] =  u00r * r0 - u00i * i0 + u01r * r1 - u01i * i1;
            ai[j0] =  u00r * i0 + u00i * r0 + u01r * i1 + u01i * r1;
            ar[j1] = -u01r * r0 - u01i * i0 + u00r * r1 + u00i * i1;
            ai[j1] = -u01r * i0 + u01i * r0 + u00r * i1 - u00i * r1;
        }
    } else if (b < 7) {                           // lane bits: warp shuffle
        const int m = 1 << (b - 2);
        const int s = (tid >> (b - 2)) & 1;
        const float cwr = u00r, cwi = s ? -u00i : u00i;
        const float cpr = s ? -u01r : u01r, cpi = u01i;
#pragma unroll
        for (int j = 0; j < 4; j++) {
            float pr = __shfl_xor_sync(0xffffffffu, ar[j], m);
            float pi = __shfl_xor_sync(0xffffffffu, ai[j], m);
            float orr = ar[j], oii = ai[j];
            ar[j] = cwr * orr - cwi * oii + cpr * pr - cpi * pi;
            ai[j] = cwr * oii + cwi * orr + cpr * pi + cpi * pr;
        }
    } else {                                      // cross-warp bits: smem
        const int m = 1 << (b - 2);
        const int s = (tid >> (b - 2)) & 1;
        float4* A4 = (float4*)B;
        float4* I4 = (float4*)(B + 1024);
        A4[tid] = make_float4(ar[0], ar[1], ar[2], ar[3]);
        I4[tid] = make_float4(ai[0], ai[1], ai[2], ai[3]);
        __syncthreads();
        float4 pa = A4[tid ^ m];
        float4 pb = I4[tid ^ m];
        float prr[4] = {pa.x, pa.y, pa.z, pa.w};
        float pii[4] = {pb.x, pb.y, pb.z, pb.w};
        const float cwr = u00r, cwi = s ? -u00i : u00i;
        const float cpr = s ? -u01r : u01r, cpi = u01i;
#pragma unroll
        for (int j = 0; j < 4; j++) {
            float orr = ar[j], oii = ai[j];
            ar[j] = cwr * orr - cwi * oii + cpr * prr[j] - cpi * pii[j];
            ai[j] = cwr * oii + cwi * orr + cpr * pii[j] + cpi * prr[j];
        }
        __syncthreads();
    }
}

__device__ __forceinline__ void apply_crx(int pc, int pt, float c, float s,
                                          float ar[4], float ai[4],
                                          int tid, float* B) {
    const bool tc = (pc >= 2) ? (((tid >> (pc - 2)) & 1) != 0) : true;
    if (pt < 2) {                                 // local target
#pragma unroll
        for (int t = 0; t < 2; t++) {
            int j0 = (pt == 0) ? t * 2 : t;
            int j1 = j0 | (1 << pt);
            bool upd = tc && (pc < 2 ? (((j0 >> pc) & 1) != 0) : true);
            if (upd) {
                float r0 = ar[j0], i0 = ai[j0], r1 = ar[j1], i1 = ai[j1];
                ar[j0] = c * r0 + s * i1;  ai[j0] = c * i0 - s * r1;
                ar[j1] = c * r1 + s * i0;  ai[j1] = c * i1 - s * r0;
            }
        }
    } else if (pt < 7) {                          // lane target: shuffle
        const int m = 1 << (pt - 2);
#pragma unroll
        for (int j = 0; j < 4; j++) {
            float pr = __shfl_xor_sync(0xffffffffu, ar[j], m);
            float pi = __shfl_xor_sync(0xffffffffu, ai[j], m);
            bool upd = tc && (pc < 2 ? (((j >> pc) & 1) != 0) : true);
            if (upd) {
                float orr = ar[j], oii = ai[j];
                ar[j] = c * orr + s * pi;
                ai[j] = c * oii - s * pr;
            }
        }
    } else {                                      // cross-warp target: smem
        const int m = 1 << (pt - 2);
        float4* A4 = (float4*)B;
        float4* I4 = (float4*)(B + 1024);
        A4[tid] = make_float4(ar[0], ar[1], ar[2], ar[3]);
        I4[tid] = make_float4(ai[0], ai[1], ai[2], ai[3]);
        __syncthreads();
        float4 pa = A4[tid ^ m];
        float4 pb = I4[tid ^ m];
        float prr[4] = {pa.x, pa.y, pa.z, pa.w};
        float pii[4] = {pb.x, pb.y, pb.z, pb.w};
#pragma unroll
        for (int j = 0; j < 4; j++) {
            bool upd = tc && (pc < 2 ? (((j >> pc) & 1) != 0) : true);
            if (upd) {
                float orr = ar[j], oii = ai[j];
                ar[j] = c * orr + s * pii[j];
                ai[j] = c * oii - s * prr[j];
            }
        }
        __syncthreads();
    }
}

__global__ __launch_bounds__(256, 4)
void qsb_circuit_kernel(const float* __restrict__ x,
                        const float* __restrict__ W1, const float* __restrict__ b1,
                        const float* __restrict__ W2, const float* __restrict__ b2,
                        const float* __restrict__ W3, const float* __restrict__ b3,
                        const float* __restrict__ base1, const float* __restrict__ base2,
                        const float* __restrict__ base3) {
    __shared__ float sx[FD];
    __shared__ float gc[NP], gs[NP];
    __shared__ float buf[2048];
    __shared__ float wred[8][NOUT];

    const int tid   = threadIdx.x;
    const int batch = blockIdx.x;
    const int g     = blockIdx.y;                 // branch 0..2
    const int lane  = tid & 31;
    const int warp  = tid >> 5;                   // 0..7

    sx[tid] = x[batch * FD + tid];

    const float* W  = (g == 0) ? W1 : ((g == 1) ? W2 : W3);
    const float* bb = (g == 0) ? b1 : ((g == 1) ? b2 : b3);
    const float* ba = (g == 0) ? base1 : ((g == 1) ? base2 : base3);
    __syncthreads();

    // ---- params: pipelined warp-per-row GEMV + sigmoid -> (cos,sin)(th/2) ----
    {
        const float4* xv = (const float4*)sx;
        const float4 x0 = xv[lane * 2];
        const float4 x1 = xv[lane * 2 + 1];
        int p = warp;
        const float4* Wv = (const float4*)(W + p * FD);
        float4 w0 = Wv[lane * 2], w1 = Wv[lane * 2 + 1];
        while (p < NP) {
            const int pn = p + 8;
            float4 nw0, nw1;
            if (pn < NP) {
                const float4* Wn = (const float4*)(W + pn * FD);
                nw0 = Wn[lane * 2]; nw1 = Wn[lane * 2 + 1];
            }
            float acc = w0.x * x0.x + w0.y * x0.y + w0.z * x0.z + w0.w * x0.w
                      + w1.x * x1.x + w1.y * x1.y + w1.z * x1.z + w1.w * x1.w;
#pragma unroll
            for (int o = 16; o; o >>= 1)
                acc += __shfl_down_sync(0xffffffffu, acc, o);
            if (lane == 0) {
                float t     = acc + bb[p] + ba[p];
                float sig   = 1.f / (1.f + __expf(-t));
                float theta = sig * TWO_PI_F;
                float sv, cv;
                __sincosf(0.5f * theta, &sv, &cv);
                gc[p] = cv; gs[p] = sv;
            }
            w0 = nw0; w1 = nw1; p = pn;
        }
    }

    // ---- state in registers ----
    float ar[4], ai[4];
#pragma unroll
    for (int j = 0; j < 4; j++) { ar[j] = 0.f; ai[j] = 0.f; }
    if (tid == 0) ar[0] = 1.f;
    __syncthreads();

    int idx = 0;
#pragma unroll
    for (int layer = 0; layer < 2; layer++) {
#pragma unroll
        for (int w = 0; w < NQ; w++) {
            const int b = 9 - w;
            float c0 = gc[idx],     s0 = gs[idx];
            float c1 = gc[idx + 1], s1 = gs[idx + 1];
            float cz = gc[idx + 2], sz = gs[idx + 2];
            idx += 3;
            // Fused U = Rz*Ry*Rx (SU(2): u00, u01)
            float u00r =  cz * c1 * c0 + sz * s1 * s0;
            float u00i =  cz * s1 * s0 - sz * c1 * c0;
            float u01r = -(cz * s1 * c0 + sz * c1 * s0);
            float u01i =  sz * s1 * c0 - cz * c1 * s0;
            apply_u(b, u00r, u00i, u01r, u01i, ar, ai, tid, buf);
        }
#pragma unroll
        for (int i = 0; i < NQ; i++) {
            apply_crx(9 - i, 9 - ((i + 1) % NQ), gc[idx], gs[idx], ar, ai, tid, buf);
            idx++;
        }
#pragma unroll
        for (int i = NQ - 1; i >= 0; i--) {
            apply_crx(9 - i, 9 - ((i + 9) % NQ), gc[idx], gs[idx], ar, ai, tid, buf);
            idx++;
        }
    }

    // ---- dump state, expectations ----
    {
        float4* A4 = (float4*)buf;
        float4* I4 = (float4*)(buf + 1024);
        A4[tid] = make_float4(ar[0], ar[1], ar[2], ar[3]);
        I4[tid] = make_float4(ai[0], ai[1], ai[2], ai[3]);
        __syncthreads();
    }
#pragma unroll
    for (int w = 0; w < NQ; w++) {
        const int p = 9 - w;
        float zr = 0.f, zi = 0.f, pz = 0.f;
#pragma unroll
        for (int kk = 0; kk < 2; kk++) {
            int k  = tid + kk * 256;
            int i0 = ((k >> p) << (p + 1)) | (k & ((1 << p) - 1));
            int i1 = i0 | (1 << p);
            float r0 = buf[i0], m0 = buf[1024 + i0];
            float r1 = buf[i1], m1 = buf[1024 + i1];
            zr += r0 * r1 + m0 * m1;
            zi += r0 * m1 - m0 * r1;
            pz += (r0 * r0 + m0 * m0) - (r1 * r1 + m1 * m1);
        }
#pragma unroll
        for (int o = 16; o; o >>= 1) {
            zr += __shfl_down_sync(0xffffffffu, zr, o);
            zi += __shfl_down_sync(0xffffffffu, zi, o);
            pz += __shfl_down_sync(0xffffffffu, pz, o);
        }
        if (lane == 0) {
            wred[warp][w]          = zr;
            wred[warp][NQ + w]     = zi;
            wred[warp][2 * NQ + w] = pz;
        }
    }
    __syncthreads();
    if (tid < NOUT) {
        float a = 0.f;
#pragma unroll
        for (int q = 0; q < 8; q++) a += wred[q][tid];
        g_mres[g][batch][tid] = (tid < 2 * NQ) ? 2.f * a : a;
    }
}

// ---------------------------------------------------------------------------
// Combine kernel: 7680 outputs.
// ---------------------------------------------------------------------------
__global__ void qsb_combine_kernel(const float* __restrict__ alpha_r,
                                   const float* __restrict__ alpha_i,
                                   const float* __restrict__ beta_r,
                                   const float* __restrict__ beta_i,
                                   const float* __restrict__ gamma_r,
                                   const float* __restrict__ gamma_i,
                                   float* __restrict__ out) {
    int i = blockIdx.x * 256 + threadIdx.x;
    if (i >= 256 * NOUT) return;
    int b = i / NOUT;
    int o = i - b * NOUT;
    float arv = alpha_r[0], aiv = alpha_i[0];
    float brv = beta_r[0],  biv = beta_i[0];
    float grv = gamma_r[0], giv = gamma_i[0];
    float nrm = sqrtf(arv * arv + aiv * aiv + brv * brv + biv * biv +
                      grv * grv + giv * giv + 1e-9f);
    float inv = 1.f / nrm;
    float m0 = g_mres[0][b][o], m1 = g_mres[1][b][o], m2 = g_mres[2][b][o];
    float re = (arv * m0 + brv * m1 + grv * m2) * inv;
    float im = (aiv * m0 + biv * m1 + giv * m2) * inv;
    out[i] = sqrtf(re * re + im * im);
}

extern "C" void kernel_launch(void* const* d_in, const int* in_sizes, int n_in,
                              void* d_out, int out_size) {
    const float* x      = (const float*)d_in[0];
    const float* W1     = (const float*)d_in[1];
    const float* b1     = (const float*)d_in[2];
    const float* W2     = (const float*)d_in[3];
    const float* b2     = (const float*)d_in[4];
    const float* W3     = (const float*)d_in[5];
    const float* b3     = (const float*)d_in[6];
    const float* base1  = (const float*)d_in[7];
    const float* base2  = (const float*)d_in[8];
    const float* base3  = (const float*)d_in[9];
    const float* ar     = (const float*)d_in[10];
    const float* ai     = (const float*)d_in[11];
    const float* br     = (const float*)d_in[12];
    const float* bi     = (const float*)d_in[13];
    const float* gr     = (const float*)d_in[14];
    const float* gi     = (const float*)d_in[15];
    float* out = (float*)d_out;

    dim3 grid(256, 3);
    qsb_circuit_kernel<<<grid, 256>>>(x, W1, b1, W2, b2, W3, b3,
                                      base1, base2, base3);
    qsb_combine_kernel<<<30, 256>>>(ar, ai, br, bi, gr, gi, out);
}